// round 5
// baseline (speedup 1.0000x reference)
#include <cuda_runtime.h>
#include <math.h>
#include <float.h>
#include <limits.h>

#define NB     32
#define NM     10000
#define ND     512
#define KTOP   5
#define RV     32768          // 32*32*32 voxels per slot
#define RV4    8192           // in float4
#define BN     64             // m-tile per block (== blockDim.x)
#define KC     64             // k-chunk == per-z slice
#define KP     68             // smem row pad: 272B stride -> phase-conflict-free LDS.128
#define KSPLIT 8

typedef unsigned long long ull;

// packed fp32x2 FMA (sm_10x FFMA2) — full fp32 precision per lane
#define FMA_F32X2(d, a, b, c) \
    asm("fma.rn.f32x2 %0, %1, %2, %3;" : "=l"(d) : "l"(a), "l"(b), "l"(c))

__device__ __forceinline__ float ull_sum2(ull v) {
    return __uint_as_float((unsigned)v) + __uint_as_float((unsigned)(v >> 32));
}

// ---- device scratch ----
__device__ float g_part[KSPLIT * NB * NM];   // partial dot [z][b][m]  (10.24 MB)
__device__ float g_kq[KSPLIT * NM];          // partial ||k||^2 [z][m]
__device__ float g_invx[NB];
__device__ int   g_topidx[NB * KTOP];

// ---------------- kernel 0: 1/||x_b|| ----------------
__global__ void xnorm_kernel(const float* __restrict__ x) {
    int b    = threadIdx.x >> 5;
    int lane = threadIdx.x & 31;
    const float4* x4 = reinterpret_cast<const float4*>(x) + b * (ND / 4);
    float s = 0.f;
#pragma unroll
    for (int j = 0; j < 4; ++j) {
        float4 v = x4[j * 32 + lane];
        s += v.x * v.x + v.y * v.y + v.z * v.z + v.w * v.w;
    }
#pragma unroll
    for (int o = 16; o > 0; o >>= 1) s += __shfl_xor_sync(0xffffffffu, s, o);
    if (lane == 0) g_invx[b] = 1.f / fmaxf(sqrtf(s), 1e-12f);
}

// ---------------- kernel 1: sim partials (K-split x8) ----------------
// Grid (157, 4, 8), 64 threads. Thread owns m-col m0+tid, 8 b-rows, 64 k.
__global__ __launch_bounds__(64) void sim_stage(const float* __restrict__ x,
                                                const float* __restrict__ keys) {
    __shared__ float xs[8 * KP];
    __shared__ float ks[BN * KP];

    const int tid = threadIdx.x;
    const int m0  = blockIdx.x * BN;
    const int b0  = blockIdx.y * 8;
    const int k0_4 = blockIdx.z * (KC / 4);
    const int gm  = m0 + tid;

    // x chunk: 8 rows x 16 float4, 2 per thread (coalesced)
    {
        const float4* xg = reinterpret_cast<const float4*>(x);
#pragma unroll
        for (int t = 0; t < 2; ++t) {
            int idx = tid + t * 64;
            int row = idx >> 4, c4 = idx & 15;
            *reinterpret_cast<float4*>(xs + row * KP + c4 * 4) =
                xg[(b0 + row) * (ND / 4) + k0_4 + c4];
        }
    }
    // key chunk: 64 rows x 16 float4, 16 per thread (coalesced, zero-pad)
    {
        const float4* kg = reinterpret_cast<const float4*>(keys);
#pragma unroll
        for (int t = 0; t < 16; ++t) {
            int idx = tid + t * 64;
            int row = idx >> 4, c4 = idx & 15;
            int gr  = m0 + row;
            float4 v = make_float4(0.f, 0.f, 0.f, 0.f);
            if (gr < NM) v = kg[gr * (ND / 4) + k0_4 + c4];
            *reinterpret_cast<float4*>(ks + row * KP + c4 * 4) = v;
        }
    }
    __syncthreads();

    ull acc2[8] = {};
    ull kq2 = 0;

    // per kk: 1 LDS.128 ka + 8 broadcast LDS.128 xa + 18 FFMA2
    const ulonglong2* kr2 = reinterpret_cast<const ulonglong2*>(ks + tid * KP);
#pragma unroll 8
    for (int kk = 0; kk < KC / 4; ++kk) {
        ulonglong2 ka = kr2[kk];
        FMA_F32X2(kq2, ka.x, ka.x, kq2);         // ||k||^2 from registers
        FMA_F32X2(kq2, ka.y, ka.y, kq2);
#pragma unroll
        for (int b = 0; b < 8; ++b) {
            ulonglong2 xa = *reinterpret_cast<const ulonglong2*>(xs + b * KP + kk * 4);
            FMA_F32X2(acc2[b], xa.x, ka.x, acc2[b]);
            FMA_F32X2(acc2[b], xa.y, ka.y, acc2[b]);
        }
    }

    if (gm < NM) {
#pragma unroll
        for (int b = 0; b < 8; ++b)
            g_part[(blockIdx.z * NB + b0 + b) * NM + gm] = ull_sum2(acc2[b]);
        if (blockIdx.y == 0)
            g_kq[blockIdx.z * NM + gm] = ull_sum2(kq2);
    }
}

// ---------------- kernel 2: fused 8-way reduce + normalize + top-5 ----------------
// One 1024-thread block per b. Tie-break matches jax.lax.top_k.
__global__ __launch_bounds__(1024) void topk_fused(float* __restrict__ out,
                                                   long long out_size) {
    __shared__ float sv[1024 * KTOP];
    __shared__ int   si[1024 * KTOP];
    __shared__ float wv[32];
    __shared__ int   wi[32];
    __shared__ int   wp[32];

    const int b = blockIdx.x, tid = threadIdx.x;
    const int lane = tid & 31, warp = tid >> 5;
    const float invx = g_invx[b];

    float v[KTOP]; int ix[KTOP];
#pragma unroll
    for (int p = 0; p < KTOP; ++p) { v[p] = -FLT_MAX; ix[p] = INT_MAX; }

    for (int i = tid; i < NM; i += 1024) {
        float dot = 0.f, kq = 0.f;
#pragma unroll
        for (int z = 0; z < KSPLIT; ++z) {
            dot += g_part[(z * NB + b) * NM + i];
            kq  += g_kq[z * NM + i];
        }
        float val = dot * invx * (1.f / fmaxf(sqrtf(kq), 1e-12f));
        if (val > v[KTOP - 1]) {                 // ascending i -> ties keep lower idx
            v[KTOP - 1] = val; ix[KTOP - 1] = i;
#pragma unroll
            for (int q = KTOP - 1; q > 0; --q) {
                if (v[q] > v[q - 1]) {
                    float tv = v[q]; v[q] = v[q - 1]; v[q - 1] = tv;
                    int   ti = ix[q]; ix[q] = ix[q - 1]; ix[q - 1] = ti;
                }
            }
        }
    }
#pragma unroll
    for (int p = 0; p < KTOP; ++p) { sv[p * 1024 + tid] = v[p]; si[p * 1024 + tid] = ix[p]; }
    __syncthreads();

    for (int k = 0; k < KTOP; ++k) {
        float bv = -FLT_MAX; int bi = INT_MAX; int bp = -1;
#pragma unroll
        for (int t = 0; t < KTOP; ++t) {
            int j = t * 1024 + tid;
            float vv = sv[j]; int ii = si[j];
            if (vv > bv || (vv == bv && ii < bi)) { bv = vv; bi = ii; bp = j; }
        }
#pragma unroll
        for (int o = 16; o > 0; o >>= 1) {
            float ov = __shfl_down_sync(0xffffffffu, bv, o);
            int   oi = __shfl_down_sync(0xffffffffu, bi, o);
            int   op = __shfl_down_sync(0xffffffffu, bp, o);
            if (ov > bv || (ov == bv && oi < bi)) { bv = ov; bi = oi; bp = op; }
        }
        if (lane == 0) { wv[warp] = bv; wi[warp] = bi; wp[warp] = bp; }
        __syncthreads();
        if (tid == 0) {
            float fv = wv[0]; int fi = wi[0]; int fp = wp[0];
#pragma unroll
            for (int w = 1; w < 32; ++w) {
                if (wv[w] > fv || (wv[w] == fv && wi[w] < fi)) {
                    fv = wv[w]; fi = wi[w]; fp = wp[w];
                }
            }
            g_topidx[b * KTOP + k] = fi;
            sv[fp] = -FLT_MAX;                   // mask winner
            const long long base = (long long)NB * KTOP * RV;
            if (out_size >= base + 2LL * NB * KTOP) {
                out[base + b * KTOP + k]             = (float)fi;
                out[base + NB * KTOP + b * KTOP + k] = fv;
            }
        }
        __syncthreads();
    }
}

// ---------------- kernel 3: gather (8 float4 in flight per thread) ----------------
// 640 blocks x 256 thr x 8 float4 == 160 slots * 8192 float4 exactly.
// slot stride 20 -> per-thread slots slot0 + 20j, constant offset.
__global__ __launch_bounds__(256) void gather_kernel(const float* __restrict__ mv,
                                                     float* __restrict__ out) {
    const int i0    = blockIdx.x * 256 + threadIdx.x;   // float4 index in [0, 163840)
    const int slot0 = i0 >> 13;                          // /8192 -> [0, 20)
    const int off   = i0 & 8191;

    int idx[8];
#pragma unroll
    for (int j = 0; j < 8; ++j) idx[j] = g_topidx[slot0 + j * 20];

    const float4* src = reinterpret_cast<const float4*>(mv);
    float4*       dst = reinterpret_cast<float4*>(out);
    float4 r[8];
#pragma unroll
    for (int j = 0; j < 8; ++j) r[j] = src[(long long)idx[j] * RV4 + off];
#pragma unroll
    for (int j = 0; j < 8; ++j) dst[(long long)(slot0 + j * 20) * RV4 + off] = r[j];
}

extern "C" void kernel_launch(void* const* d_in, const int* in_sizes, int n_in,
                              void* d_out, int out_size) {
    const float* x    = (const float*)d_in[0];
    const float* keys = (const float*)d_in[1];
    const float* mv   = (const float*)d_in[2];
    float* out = (float*)d_out;

    xnorm_kernel<<<1, 1024>>>(x);
    dim3 simgrid((NM + BN - 1) / BN, NB / 8, KSPLIT);
    sim_stage<<<simgrid, BN>>>(x, keys);
    topk_fused<<<NB, 1024>>>(out, (long long)out_size);
    gather_kernel<<<640, 256>>>(mv, out);
}

// round 6
// speedup vs baseline: 1.0860x; 1.0860x over previous
#include <cuda_runtime.h>
#include <math.h>
#include <float.h>
#include <limits.h>

#define NB     32
#define NM     10000
#define ND     512
#define KTOP   5
#define RV     32768          // 32*32*32 voxels per slot
#define RV4    8192           // in float4
#define BN     64             // m-tile per block (== blockDim.x)
#define KC     64             // k-chunk
#define KP     68             // smem row pad: 272B stride -> phase-conflict-free LDS.128
#define KSPLIT 2
#define KHALF  (ND / KSPLIT)  // 256
#define NCHUNK (KHALF / KC)   // 4

typedef unsigned long long ull;

// packed fp32x2 FMA (sm_10x FFMA2) — full fp32 precision per lane
#define FMA_F32X2(d, a, b, c) \
    asm("fma.rn.f32x2 %0, %1, %2, %3;" : "=l"(d) : "l"(a), "l"(b), "l"(c))

__device__ __forceinline__ float ull_sum2(ull v) {
    return __uint_as_float((unsigned)v) + __uint_as_float((unsigned)(v >> 32));
}

// ---- device scratch ----
__device__ float g_part[KSPLIT * NB * NM];   // partial dot [z][b][m]
__device__ float g_kq[KSPLIT * NM];          // partial ||k||^2 [z][m]
__device__ float g_invx[NB];
__device__ int   g_topidx[NB * KTOP];

// ---------------- kernel 0: 1/||x_b|| ----------------
__global__ void xnorm_kernel(const float* __restrict__ x) {
    int b    = threadIdx.x >> 5;
    int lane = threadIdx.x & 31;
    const float4* x4 = reinterpret_cast<const float4*>(x) + b * (ND / 4);
    float s = 0.f;
#pragma unroll
    for (int j = 0; j < 4; ++j) {
        float4 v = x4[j * 32 + lane];
        s += v.x * v.x + v.y * v.y + v.z * v.z + v.w * v.w;
    }
#pragma unroll
    for (int o = 16; o > 0; o >>= 1) s += __shfl_xor_sync(0xffffffffu, s, o);
    if (lane == 0) g_invx[b] = 1.f / fmaxf(sqrtf(s), 1e-12f);
}

// ---------------- kernel 1: sim partials (K-split x2, pipelined) ----------------
// Grid (157, 4, 2), 64 threads. Thread owns m-col m0+tid, 8 b-rows, 256 k.
// Register double-buffer: prefetch chunk c+1 (keys 16 f4, x 2 f4) during compute of c.
__global__ __launch_bounds__(64) void sim_stage(const float* __restrict__ x,
                                                const float* __restrict__ keys) {
    __shared__ float xs[8 * KP];
    __shared__ float ks[BN * KP];

    const int tid = threadIdx.x;
    const int m0  = blockIdx.x * BN;
    const int b0  = blockIdx.y * 8;
    const int kz4 = blockIdx.z * (KHALF / 4);
    const int gm  = m0 + tid;

    const float4* xg = reinterpret_cast<const float4*>(x);
    const float4* kg = reinterpret_cast<const float4*>(keys);

    // per-thread load coordinates (fixed across chunks)
    const int xrow = tid >> 4, xc4 = tid & 15;             // +t*64 -> 2 x loads
    int   krow[16], kc4_[16];
    bool  kok[16];
#pragma unroll
    for (int t = 0; t < 16; ++t) {
        int idx = tid + t * 64;
        krow[t] = idx >> 4; kc4_[t] = idx & 15;
        kok[t]  = (m0 + krow[t]) < NM;
    }

    float4 kbuf[16], xbuf[2];

    // prologue: fetch chunk 0
    {
        const int k0_4 = kz4;
#pragma unroll
        for (int t = 0; t < 2; ++t)
            xbuf[t] = xg[(b0 + (tid + t * 64 >> 4)) * (ND / 4) + k0_4 + ((tid + t * 64) & 15)];
#pragma unroll
        for (int t = 0; t < 16; ++t) {
            float4 v = make_float4(0.f, 0.f, 0.f, 0.f);
            if (kok[t]) v = kg[(m0 + krow[t]) * (ND / 4) + k0_4 + kc4_[t]];
            kbuf[t] = v;
        }
    }

    ull acc2[8] = {};
    ull kq2 = 0;

    for (int c = 0; c < NCHUNK; ++c) {
        // stage current chunk to smem
#pragma unroll
        for (int t = 0; t < 2; ++t) {
            int idx = tid + t * 64;
            *reinterpret_cast<float4*>(xs + (idx >> 4) * KP + (idx & 15) * 4) = xbuf[t];
        }
#pragma unroll
        for (int t = 0; t < 16; ++t)
            *reinterpret_cast<float4*>(ks + krow[t] * KP + kc4_[t] * 4) = kbuf[t];
        __syncthreads();

        // prefetch next chunk into registers (overlaps compute below)
        if (c + 1 < NCHUNK) {
            const int k0_4 = kz4 + (c + 1) * (KC / 4);
#pragma unroll
            for (int t = 0; t < 2; ++t) {
                int idx = tid + t * 64;
                xbuf[t] = xg[(b0 + (idx >> 4)) * (ND / 4) + k0_4 + (idx & 15)];
            }
#pragma unroll
            for (int t = 0; t < 16; ++t) {
                float4 v = make_float4(0.f, 0.f, 0.f, 0.f);
                if (kok[t]) v = kg[(m0 + krow[t]) * (ND / 4) + k0_4 + kc4_[t]];
                kbuf[t] = v;
            }
        }

        // compute: per kk = 1 LDS.128 ka + 8 broadcast LDS.128 xa + 18 FFMA2
        const ulonglong2* kr2 = reinterpret_cast<const ulonglong2*>(ks + tid * KP);
#pragma unroll
        for (int kk = 0; kk < KC / 4; ++kk) {
            ulonglong2 ka = kr2[kk];
            FMA_F32X2(kq2, ka.x, ka.x, kq2);
            FMA_F32X2(kq2, ka.y, ka.y, kq2);
#pragma unroll
            for (int b = 0; b < 8; ++b) {
                ulonglong2 xa = *reinterpret_cast<const ulonglong2*>(xs + b * KP + kk * 4);
                FMA_F32X2(acc2[b], xa.x, ka.x, acc2[b]);
                FMA_F32X2(acc2[b], xa.y, ka.y, acc2[b]);
            }
        }
        __syncthreads();
    }

    if (gm < NM) {
#pragma unroll
        for (int b = 0; b < 8; ++b)
            g_part[(blockIdx.z * NB + b0 + b) * NM + gm] = ull_sum2(acc2[b]);
        if (blockIdx.y == 0)
            g_kq[blockIdx.z * NM + gm] = ull_sum2(kq2);
    }
}

// ---------------- kernel 2: fused normalize + top-5 ----------------
// One 1024-thread block per b. Tie-break matches jax.lax.top_k.
__global__ __launch_bounds__(1024) void topk_fused(float* __restrict__ out,
                                                   long long out_size) {
    __shared__ float sv[1024 * KTOP];
    __shared__ int   si[1024 * KTOP];
    __shared__ float wv[32];
    __shared__ int   wi[32];
    __shared__ int   wp[32];

    const int b = blockIdx.x, tid = threadIdx.x;
    const int lane = tid & 31, warp = tid >> 5;
    const float invx = g_invx[b];

    float v[KTOP]; int ix[KTOP];
#pragma unroll
    for (int p = 0; p < KTOP; ++p) { v[p] = -FLT_MAX; ix[p] = INT_MAX; }

    const float* p0 = g_part + b * NM;
    const float* p1 = g_part + (NB + b) * NM;
    for (int i = tid; i < NM; i += 1024) {
        float dot = p0[i] + p1[i];
        float kq  = g_kq[i] + g_kq[NM + i];
        float val = dot * invx * (1.f / fmaxf(sqrtf(kq), 1e-12f));
        if (val > v[KTOP - 1]) {                 // ascending i -> ties keep lower idx
            v[KTOP - 1] = val; ix[KTOP - 1] = i;
#pragma unroll
            for (int q = KTOP - 1; q > 0; --q) {
                if (v[q] > v[q - 1]) {
                    float tv = v[q]; v[q] = v[q - 1]; v[q - 1] = tv;
                    int   ti = ix[q]; ix[q] = ix[q - 1]; ix[q - 1] = ti;
                }
            }
        }
    }
#pragma unroll
    for (int p = 0; p < KTOP; ++p) { sv[p * 1024 + tid] = v[p]; si[p * 1024 + tid] = ix[p]; }
    __syncthreads();

    for (int k = 0; k < KTOP; ++k) {
        float bv = -FLT_MAX; int bi = INT_MAX; int bp = -1;
#pragma unroll
        for (int t = 0; t < KTOP; ++t) {
            int j = t * 1024 + tid;
            float vv = sv[j]; int ii = si[j];
            if (vv > bv || (vv == bv && ii < bi)) { bv = vv; bi = ii; bp = j; }
        }
#pragma unroll
        for (int o = 16; o > 0; o >>= 1) {
            float ov = __shfl_down_sync(0xffffffffu, bv, o);
            int   oi = __shfl_down_sync(0xffffffffu, bi, o);
            int   op = __shfl_down_sync(0xffffffffu, bp, o);
            if (ov > bv || (ov == bv && oi < bi)) { bv = ov; bi = oi; bp = op; }
        }
        if (lane == 0) { wv[warp] = bv; wi[warp] = bi; wp[warp] = bp; }
        __syncthreads();
        if (tid == 0) {
            float fv = wv[0]; int fi = wi[0]; int fp = wp[0];
#pragma unroll
            for (int w = 1; w < 32; ++w) {
                if (wv[w] > fv || (wv[w] == fv && wi[w] < fi)) {
                    fv = wv[w]; fi = wi[w]; fp = wp[w];
                }
            }
            g_topidx[b * KTOP + k] = fi;
            sv[fp] = -FLT_MAX;                   // mask winner
            const long long base = (long long)NB * KTOP * RV;
            if (out_size >= base + 2LL * NB * KTOP) {
                out[base + b * KTOP + k]             = (float)fi;
                out[base + NB * KTOP + b * KTOP + k] = fv;
            }
        }
        __syncthreads();
    }
}

// ---------------- kernel 3: gather (exact-fit grid-stride, 4 f4/thread) ----------------
// 1280 blocks x 256 thr x 4 float4 == 160 slots * 8192 float4 exactly.
__global__ __launch_bounds__(256) void gather_kernel(const float* __restrict__ mv,
                                                     float* __restrict__ out) {
    const int i0    = blockIdx.x * 256 + threadIdx.x;   // float4 index
    const int slot0 = i0 >> 13;                          // /8192
    const int off   = i0 & 8191;

    int idx[4];
#pragma unroll
    for (int j = 0; j < 4; ++j) idx[j] = g_topidx[slot0 + j * 40];

    const float4* src = reinterpret_cast<const float4*>(mv);
    float4*       dst = reinterpret_cast<float4*>(out);
    float4 r[4];
#pragma unroll
    for (int j = 0; j < 4; ++j) r[j] = src[(long long)idx[j] * RV4 + off];
#pragma unroll
    for (int j = 0; j < 4; ++j) dst[(long long)(slot0 + j * 40) * RV4 + off] = r[j];
}

extern "C" void kernel_launch(void* const* d_in, const int* in_sizes, int n_in,
                              void* d_out, int out_size) {
    const float* x    = (const float*)d_in[0];
    const float* keys = (const float*)d_in[1];
    const float* mv   = (const float*)d_in[2];
    float* out = (float*)d_out;

    xnorm_kernel<<<1, 1024>>>(x);
    dim3 simgrid((NM + BN - 1) / BN, NB / 8, KSPLIT);
    sim_stage<<<simgrid, BN>>>(x, keys);
    topk_fused<<<NB, 1024>>>(out, (long long)out_size);
    gather_kernel<<<1280, 256>>>(mv, out);
}

// round 7
// speedup vs baseline: 1.0868x; 1.0007x over previous
#include <cuda_runtime.h>
#include <math.h>
#include <float.h>
#include <limits.h>

#define NB     32
#define NM     10000
#define ND     512
#define KTOP   5
#define RV     32768          // 32*32*32 voxels per slot
#define RV4    8192           // in float4
#define BM     64             // m-tile per block
#define KC     64             // k-chunk (== per-z slice)
#define KP     68             // smem row pad: 272B stride -> phase-conflict-free LDS.128
#define KSPLIT 8              // 512 / KC

typedef unsigned long long ull;

// packed fp32x2 FMA (sm_10x FFMA2) — full fp32 precision per lane
#define FMA_F32X2(d, a, b, c) \
    asm("fma.rn.f32x2 %0, %1, %2, %3;" : "=l"(d) : "l"(a), "l"(b), "l"(c))

__device__ __forceinline__ float ull_sum2(ull v) {
    return __uint_as_float((unsigned)v) + __uint_as_float((unsigned)(v >> 32));
}

// ---- device scratch ----
__device__ float g_part[KSPLIT * NB * NM];   // partial dot [z][b][m] (10.24 MB, L2-resident)
__device__ float g_kq[KSPLIT * NM];          // partial ||k||^2 [z][m]
__device__ float g_invx[NB];
__device__ int   g_topidx[NB * KTOP];

// ---------------- kernel 0: 1/||x_b|| ----------------
__global__ void xnorm_kernel(const float* __restrict__ x) {
    int b    = threadIdx.x >> 5;
    int lane = threadIdx.x & 31;
    const float4* x4 = reinterpret_cast<const float4*>(x) + b * (ND / 4);
    float s = 0.f;
#pragma unroll
    for (int j = 0; j < 4; ++j) {
        float4 v = x4[j * 32 + lane];
        s += v.x * v.x + v.y * v.y + v.z * v.z + v.w * v.w;
    }
#pragma unroll
    for (int o = 16; o > 0; o >>= 1) s += __shfl_xor_sync(0xffffffffu, s, o);
    if (lane == 0) g_invx[b] = 1.f / fmaxf(sqrtf(s), 1e-12f);
}

// ---------------- kernel 1: sim partials ----------------
// Grid (157, 8). Block 256 thr = 8 warps: warp-pair wp owns b-group wp (8 b-rows),
// all warp-pairs share the SAME ks tile (64 m x 64 k). Keys read exactly once.
// Thread: m = m0 + (warp&1)*32 + lane, 8 b-rows, 64 k.
__global__ __launch_bounds__(256) void sim_stage(const float* __restrict__ x,
                                                 const float* __restrict__ keys) {
    __shared__ float xs[NB * KP];     // all 32 b rows (8.7 KB)
    __shared__ float ks[BM * KP];     // 64 m rows (17.4 KB)

    const int tid  = threadIdx.x;
    const int m0   = blockIdx.x * BM;
    const int z    = blockIdx.y;
    const int k0_4 = z * (KC / 4);
    const int warp = tid >> 5, lane = tid & 31;
    const int bg   = warp >> 1;                   // b-group 0..3
    const int b0   = bg * 8;
    const int m_l  = ((warp & 1) << 5) | lane;    // 0..63
    const int gm   = m0 + m_l;

    // fill ks: 64 rows x 16 float4 = 1024, 4 per thread (coalesced, read-once -> ldcs)
    {
        const float4* kg = reinterpret_cast<const float4*>(keys);
#pragma unroll
        for (int t = 0; t < 4; ++t) {
            int idx = tid + t * 256;
            int row = idx >> 4, c4 = idx & 15;
            int gr  = m0 + row;
            float4 v = make_float4(0.f, 0.f, 0.f, 0.f);
            if (gr < NM) v = __ldcs(kg + gr * (ND / 4) + k0_4 + c4);
            *reinterpret_cast<float4*>(ks + row * KP + c4 * 4) = v;
        }
    }
    // fill xs: 32 rows x 16 float4 = 512, 2 per thread (x is tiny + L2-hot)
    {
        const float4* xg = reinterpret_cast<const float4*>(x);
#pragma unroll
        for (int t = 0; t < 2; ++t) {
            int idx = tid + t * 256;
            int row = idx >> 4, c4 = idx & 15;
            *reinterpret_cast<float4*>(xs + row * KP + c4 * 4) =
                xg[row * (ND / 4) + k0_4 + c4];
        }
    }
    __syncthreads();

    ull acc2[8] = {};
    ull kq2 = 0;

    // per kk: 1 LDS.128 ka (conflict-free) + 8 broadcast LDS.128 xa + 16(+2) FFMA2
    const ulonglong2* kr2 = reinterpret_cast<const ulonglong2*>(ks + m_l * KP);
#pragma unroll
    for (int kk = 0; kk < KC / 4; ++kk) {
        ulonglong2 ka = kr2[kk];
        FMA_F32X2(kq2, ka.x, ka.x, kq2);          // ||k||^2 from registers
        FMA_F32X2(kq2, ka.y, ka.y, kq2);
#pragma unroll
        for (int b = 0; b < 8; ++b) {
            ulonglong2 xa =
                *reinterpret_cast<const ulonglong2*>(xs + (b0 + b) * KP + kk * 4);
            FMA_F32X2(acc2[b], xa.x, ka.x, acc2[b]);
            FMA_F32X2(acc2[b], xa.y, ka.y, acc2[b]);
        }
    }

    if (gm < NM) {
#pragma unroll
        for (int b = 0; b < 8; ++b)
            g_part[(z * NB + b0 + b) * NM + gm] = ull_sum2(acc2[b]);
        if (bg == 0)
            g_kq[z * NM + gm] = ull_sum2(kq2);
    }
}

// ---------------- kernel 2: fused 8-way reduce + normalize + top-5 ----------------
// One 1024-thread block per b. Tie-break matches jax.lax.top_k.
__global__ __launch_bounds__(1024) void topk_fused(float* __restrict__ out,
                                                   long long out_size) {
    __shared__ float sv[1024 * KTOP];
    __shared__ int   si[1024 * KTOP];
    __shared__ float wv[32];
    __shared__ int   wi[32];
    __shared__ int   wp[32];

    const int b = blockIdx.x, tid = threadIdx.x;
    const int lane = tid & 31, warp = tid >> 5;
    const float invx = g_invx[b];

    float v[KTOP]; int ix[KTOP];
#pragma unroll
    for (int p = 0; p < KTOP; ++p) { v[p] = -FLT_MAX; ix[p] = INT_MAX; }

    for (int i = tid; i < NM; i += 1024) {
        float dot = 0.f, kq = 0.f;
#pragma unroll
        for (int z = 0; z < KSPLIT; ++z) {
            dot += g_part[(z * NB + b) * NM + i];
            kq  += g_kq[z * NM + i];
        }
        float val = dot * invx * (1.f / fmaxf(sqrtf(kq), 1e-12f));
        if (val > v[KTOP - 1]) {                 // ascending i -> ties keep lower idx
            v[KTOP - 1] = val; ix[KTOP - 1] = i;
#pragma unroll
            for (int q = KTOP - 1; q > 0; --q) {
                if (v[q] > v[q - 1]) {
                    float tv = v[q]; v[q] = v[q - 1]; v[q - 1] = tv;
                    int   ti = ix[q]; ix[q] = ix[q - 1]; ix[q - 1] = ti;
                }
            }
        }
    }
#pragma unroll
    for (int p = 0; p < KTOP; ++p) { sv[p * 1024 + tid] = v[p]; si[p * 1024 + tid] = ix[p]; }
    __syncthreads();

    for (int k = 0; k < KTOP; ++k) {
        float bv = -FLT_MAX; int bi = INT_MAX; int bp = -1;
#pragma unroll
        for (int t = 0; t < KTOP; ++t) {
            int j = t * 1024 + tid;
            float vv = sv[j]; int ii = si[j];
            if (vv > bv || (vv == bv && ii < bi)) { bv = vv; bi = ii; bp = j; }
        }
#pragma unroll
        for (int o = 16; o > 0; o >>= 1) {
            float ov = __shfl_down_sync(0xffffffffu, bv, o);
            int   oi = __shfl_down_sync(0xffffffffu, bi, o);
            int   op = __shfl_down_sync(0xffffffffu, bp, o);
            if (ov > bv || (ov == bv && oi < bi)) { bv = ov; bi = oi; bp = op; }
        }
        if (lane == 0) { wv[warp] = bv; wi[warp] = bi; wp[warp] = bp; }
        __syncthreads();
        if (tid == 0) {
            float fv = wv[0]; int fi = wi[0]; int fp = wp[0];
#pragma unroll
            for (int w = 1; w < 32; ++w) {
                if (wv[w] > fv || (wv[w] == fv && wi[w] < fi)) {
                    fv = wv[w]; fi = wi[w]; fp = wp[w];
                }
            }
            g_topidx[b * KTOP + k] = fi;
            sv[fp] = -FLT_MAX;                   // mask winner
            const long long base = (long long)NB * KTOP * RV;
            if (out_size >= base + 2LL * NB * KTOP) {
                out[base + b * KTOP + k]             = (float)fi;
                out[base + NB * KTOP + b * KTOP + k] = fv;
            }
        }
        __syncthreads();
    }
}

// ---------------- kernel 3: gather (exact-fit, streaming hints) ----------------
// 1280 blocks x 256 thr x 4 float4 == 160 slots * 8192 float4 exactly.
__global__ __launch_bounds__(256) void gather_kernel(const float* __restrict__ mv,
                                                     float* __restrict__ out) {
    const int i0    = blockIdx.x * 256 + threadIdx.x;   // float4 index
    const int slot0 = i0 >> 13;                          // /8192
    const int off   = i0 & 8191;

    int idx[4];
#pragma unroll
    for (int j = 0; j < 4; ++j) idx[j] = g_topidx[slot0 + j * 40];

    const float4* src = reinterpret_cast<const float4*>(mv);
    float4*       dst = reinterpret_cast<float4*>(out);
    float4 r[4];
#pragma unroll
    for (int j = 0; j < 4; ++j) r[j] = __ldcs(src + (long long)idx[j] * RV4 + off);
#pragma unroll
    for (int j = 0; j < 4; ++j) __stcs(dst + (long long)(slot0 + j * 40) * RV4 + off, r[j]);
}

extern "C" void kernel_launch(void* const* d_in, const int* in_sizes, int n_in,
                              void* d_out, int out_size) {
    const float* x    = (const float*)d_in[0];
    const float* keys = (const float*)d_in[1];
    const float* mv   = (const float*)d_in[2];
    float* out = (float*)d_out;

    xnorm_kernel<<<1, 1024>>>(x);
    dim3 simgrid((NM + BM - 1) / BM, KSPLIT);
    sim_stage<<<simgrid, 256>>>(x, keys);
    topk_fused<<<NB, 1024>>>(out, (long long)out_size);
    gather_kernel<<<1280, 256>>>(mv, out);
}

// round 8
// speedup vs baseline: 1.1356x; 1.0450x over previous
#include <cuda_runtime.h>
#include <math.h>
#include <float.h>
#include <limits.h>

#define NB     32
#define NM     10000
#define ND     512
#define KTOP   5
#define RV     32768          // 32*32*32 voxels per slot
#define RV4    8192           // in float4
#define BM     128            // m-tile per block
#define KC     64             // k-chunk (== per-z slice)
#define KP     68             // ks row pad (floats): 272B stride -> conflict-free LDS.128
#define XP     33             // xsp row pad (float2 units): 264B -> conflict-free
#define KSPLIT 8              // 512 / KC

typedef unsigned long long ull;

// packed fp32x2 FMA (sm_10x FFMA2) — full fp32 precision per lane
#define FMA_F32X2(d, a, b, c) \
    asm("fma.rn.f32x2 %0, %1, %2, %3;" : "=l"(d) : "l"(a), "l"(b), "l"(c))

__device__ __forceinline__ float ull_sum2(ull v) {
    return __uint_as_float((unsigned)v) + __uint_as_float((unsigned)(v >> 32));
}

// ---- device scratch ----
__device__ float g_part[KSPLIT * NB * NM];   // partial dot [z][b][m]
__device__ float g_kq[KSPLIT * NM];          // partial ||k||^2 [z][m]
__device__ float g_invx[NB];
__device__ int   g_topidx[NB * KTOP];

// ---------------- kernel 0: 1/||x_b|| ----------------
__global__ void xnorm_kernel(const float* __restrict__ x) {
    int b    = threadIdx.x >> 5;
    int lane = threadIdx.x & 31;
    const float4* x4 = reinterpret_cast<const float4*>(x) + b * (ND / 4);
    float s = 0.f;
#pragma unroll
    for (int j = 0; j < 4; ++j) {
        float4 v = x4[j * 32 + lane];
        s += v.x * v.x + v.y * v.y + v.z * v.z + v.w * v.w;
    }
#pragma unroll
    for (int o = 16; o > 0; o >>= 1) s += __shfl_xor_sync(0xffffffffu, s, o);
    if (lane == 0) g_invx[b] = 1.f / fmaxf(sqrtf(s), 1e-12f);
}

// ---------------- kernel 1: sim partials ----------------
// Grid (79, 8). Block 256 thr: 128 m x 32 b x 64 k. Warp w: b-group 4w.
// Thread: 4 m (lane + j*32) x 4 b, FFMA2 over k-pairs.
// Crossbar per warp-kk: 4 LDS.128 (ka) + 8 LDS.64 (xa) = 32 cyc / 2048 FMA.
__global__ __launch_bounds__(256, 3) void sim_stage(const float* __restrict__ x,
                                                    const float* __restrict__ keys) {
    __shared__ float  ks[BM * KP];     // keys chunk [128 m][KP]     (34.8 KB)
    __shared__ float2 xsp[KC / 2 * XP];// x chunk, k-pair major [kp][b] (8.4 KB)

    const int tid  = threadIdx.x;
    const int m0   = blockIdx.x * BM;
    const int z    = blockIdx.y;
    const int k0_4 = z * (KC / 4);
    const int lane = tid & 31, w = tid >> 5;
    const int b0   = w * 4;

    // fill ks: 128 rows x 16 float4 = 2048, 8 per thread (coalesced, read-once)
    {
        const float4* kg = reinterpret_cast<const float4*>(keys);
#pragma unroll
        for (int t = 0; t < 8; ++t) {
            int idx = tid + t * 256;
            int row = idx >> 4, c4 = idx & 15;
            int gr  = m0 + row;
            float4 v = make_float4(0.f, 0.f, 0.f, 0.f);
            if (gr < NM) v = __ldcs(kg + gr * (ND / 4) + k0_4 + c4);
            *reinterpret_cast<float4*>(ks + row * KP + c4 * 4) = v;
        }
    }
    // fill xsp[kp][b] = (x[b][z*64+2kp], x[b][z*64+2kp+1]): 1024 float2, 4/thread.
    // u: b = u>>5 (fixed per warp), kp = u&31 (consecutive) -> gmem 256B coalesced,
    // STS stride XP*8=264B -> conflict-free.
    {
        const float2* xg2 = reinterpret_cast<const float2*>(x);
#pragma unroll
        for (int t = 0; t < 4; ++t) {
            int u  = tid + t * 256;
            int b  = u >> 5, kp = u & 31;
            xsp[kp * XP + b] = xg2[b * (ND / 2) + (k0_4 << 1) + kp];
        }
    }
    __syncthreads();

    ull acc2[4][4] = {};
    ull kq2[4] = {};

#pragma unroll
    for (int kk = 0; kk < KC / 4; ++kk) {
        ulonglong2 ka[4];
#pragma unroll
        for (int j = 0; j < 4; ++j)
            ka[j] = *reinterpret_cast<const ulonglong2*>(ks + (lane + j * 32) * KP + kk * 4);
        ull xa[2][4];
#pragma unroll
        for (int p = 0; p < 2; ++p)
#pragma unroll
            for (int bb = 0; bb < 4; ++bb)
                xa[p][bb] = *reinterpret_cast<const ull*>(&xsp[(kk * 2 + p) * XP + b0 + bb]);
        if (w == 0) {                  // key norms: warp 0 only (ka identical across warps)
#pragma unroll
            for (int j = 0; j < 4; ++j) {
                FMA_F32X2(kq2[j], ka[j].x, ka[j].x, kq2[j]);
                FMA_F32X2(kq2[j], ka[j].y, ka[j].y, kq2[j]);
            }
        }
#pragma unroll
        for (int j = 0; j < 4; ++j)
#pragma unroll
            for (int bb = 0; bb < 4; ++bb) {
                FMA_F32X2(acc2[j][bb], ka[j].x, xa[0][bb], acc2[j][bb]);
                FMA_F32X2(acc2[j][bb], ka[j].y, xa[1][bb], acc2[j][bb]);
            }
    }

#pragma unroll
    for (int j = 0; j < 4; ++j) {
        int gm = m0 + lane + j * 32;
        if (gm < NM) {
#pragma unroll
            for (int bb = 0; bb < 4; ++bb)
                g_part[(z * NB + b0 + bb) * NM + gm] = ull_sum2(acc2[j][bb]);
            if (w == 0) g_kq[z * NM + gm] = ull_sum2(kq2[j]);
        }
    }
}

// ---------------- kernel 2: fused 8-way reduce + normalize + top-5 ----------------
// One 1024-thread block per b. Tie-break matches jax.lax.top_k.
__global__ __launch_bounds__(1024) void topk_fused(float* __restrict__ out,
                                                   long long out_size) {
    __shared__ float sv[1024 * KTOP];
    __shared__ int   si[1024 * KTOP];
    __shared__ float wv[32];
    __shared__ int   wi[32];
    __shared__ int   wp[32];

    const int b = blockIdx.x, tid = threadIdx.x;
    const int lane = tid & 31, warp = tid >> 5;
    const float invx = g_invx[b];

    float v[KTOP]; int ix[KTOP];
#pragma unroll
    for (int p = 0; p < KTOP; ++p) { v[p] = -FLT_MAX; ix[p] = INT_MAX; }

    for (int i = tid; i < NM; i += 1024) {
        float dot = 0.f, kq = 0.f;
#pragma unroll
        for (int z = 0; z < KSPLIT; ++z) {
            dot += g_part[(z * NB + b) * NM + i];
            kq  += g_kq[z * NM + i];
        }
        float val = dot * invx * (1.f / fmaxf(sqrtf(kq), 1e-12f));
        if (val > v[KTOP - 1]) {                 // ascending i -> ties keep lower idx
            v[KTOP - 1] = val; ix[KTOP - 1] = i;
#pragma unroll
            for (int q = KTOP - 1; q > 0; --q) {
                if (v[q] > v[q - 1]) {
                    float tv = v[q]; v[q] = v[q - 1]; v[q - 1] = tv;
                    int   ti = ix[q]; ix[q] = ix[q - 1]; ix[q - 1] = ti;
                }
            }
        }
    }
#pragma unroll
    for (int p = 0; p < KTOP; ++p) { sv[p * 1024 + tid] = v[p]; si[p * 1024 + tid] = ix[p]; }
    __syncthreads();

    for (int k = 0; k < KTOP; ++k) {
        float bv = -FLT_MAX; int bi = INT_MAX; int bp = -1;
#pragma unroll
        for (int t = 0; t < KTOP; ++t) {
            int j = t * 1024 + tid;
            float vv = sv[j]; int ii = si[j];
            if (vv > bv || (vv == bv && ii < bi)) { bv = vv; bi = ii; bp = j; }
        }
#pragma unroll
        for (int o = 16; o > 0; o >>= 1) {
            float ov = __shfl_down_sync(0xffffffffu, bv, o);
            int   oi = __shfl_down_sync(0xffffffffu, bi, o);
            int   op = __shfl_down_sync(0xffffffffu, bp, o);
            if (ov > bv || (ov == bv && oi < bi)) { bv = ov; bi = oi; bp = op; }
        }
        if (lane == 0) { wv[warp] = bv; wi[warp] = bi; wp[warp] = bp; }
        __syncthreads();
        if (tid == 0) {
            float fv = wv[0]; int fi = wi[0]; int fp = wp[0];
#pragma unroll
            for (int w = 1; w < 32; ++w) {
                if (wv[w] > fv || (wv[w] == fv && wi[w] < fi)) {
                    fv = wv[w]; fi = wi[w]; fp = wp[w];
                }
            }
            g_topidx[b * KTOP + k] = fi;
            sv[fp] = -FLT_MAX;                   // mask winner
            const long long base = (long long)NB * KTOP * RV;
            if (out_size >= base + 2LL * NB * KTOP) {
                out[base + b * KTOP + k]             = (float)fi;
                out[base + NB * KTOP + b * KTOP + k] = fv;
            }
        }
        __syncthreads();
    }
}

// ---------------- kernel 3: gather (exact-fit, streaming hints) ----------------
// 1280 blocks x 256 thr x 4 float4 == 160 slots * 8192 float4 exactly.
__global__ __launch_bounds__(256) void gather_kernel(const float* __restrict__ mv,
                                                     float* __restrict__ out) {
    const int i0    = blockIdx.x * 256 + threadIdx.x;   // float4 index
    const int slot0 = i0 >> 13;                          // /8192
    const int off   = i0 & 8191;

    int idx[4];
#pragma unroll
    for (int j = 0; j < 4; ++j) idx[j] = g_topidx[slot0 + j * 40];

    const float4* src = reinterpret_cast<const float4*>(mv);
    float4*       dst = reinterpret_cast<float4*>(out);
    float4 r[4];
#pragma unroll
    for (int j = 0; j < 4; ++j) r[j] = __ldcs(src + (long long)idx[j] * RV4 + off);
#pragma unroll
    for (int j = 0; j < 4; ++j) __stcs(dst + (long long)(slot0 + j * 40) * RV4 + off, r[j]);
}

extern "C" void kernel_launch(void* const* d_in, const int* in_sizes, int n_in,
                              void* d_out, int out_size) {
    const float* x    = (const float*)d_in[0];
    const float* keys = (const float*)d_in[1];
    const float* mv   = (const float*)d_in[2];
    float* out = (float*)d_out;

    xnorm_kernel<<<1, 1024>>>(x);
    dim3 simgrid((NM + BM - 1) / BM, KSPLIT);
    sim_stage<<<simgrid, 256>>>(x, keys);
    topk_fused<<<NB, 1024>>>(out, (long long)out_size);
    gather_kernel<<<1280, 256>>>(mv, out);
}